// round 16
// baseline (speedup 1.0000x reference)
#include <cuda_runtime.h>
#include <cuda_bf16.h>
#include <cstdint>

#define NN   10240
#define NE   320000
#define BBG  64
#define NPGX 160
#define KF   16
#define DIN  25
#define DD   256
#define NBLK 148
#define NSLC 70

#if defined(__CUDA_ARCH_FEAT_SM103_ALL) || defined(__CUDA_ARCH_FEAT_SM100_ALL)
#define USE_TCGEN05 1
#else
#define USE_TCGEN05 0
#endif

// ---------------- device scratch (static, allocation-free) ----------------
__device__ int   g_bar_cnt;          // zero-init; returns to 0 after each barrier
__device__ int   g_bar_gen;          // monotonic across replays (relative compare)
__device__ int   g_mask_nz;          // idempotent atomicOr -> replay-deterministic
__device__ int   g_deg[NN];          // zero at load; reset inside scan each run
__device__ int   g_cur[NN];
__device__ int   g_off[NN + 1];
__device__ int   g_part[NBLK];
__device__ int   g_partoff[NBLK];
__device__ float g_dinv[NN];
__device__ __align__(16) int2  g_csrw[NE];   // {(src<<1)|mask, bitcast(norm)}
__device__ int   g_frag[NN];
__device__ __align__(16) float g_H[2][NN * DD];
__device__ __align__(16) float g_x32[NN * 32];   // x padded to 32 cols
// bf16 split SpMM outputs: 0=AGI_hi 1=AGI_lo 2=AGO_hi 3=AGO_lo
__device__ __align__(16) __nv_bfloat16 g_Abf[4][NN * DD];
__device__ __align__(16) __nv_bfloat16 g_Wp[3 * 6 * DD * DD];
__device__ __align__(16) __nv_bfloat16 g_A0[NN * 192];
__device__ __align__(16) __nv_bfloat16 g_W0p[DD * 192];

// ---------------- PTX helpers ----------------
__device__ __forceinline__ uint32_t smem_u32(const void* p) {
    uint32_t a;
    asm("{ .reg .u64 t; cvta.to.shared.u64 t, %1; cvt.u32.u64 %0, t; }" : "=r"(a) : "l"(p));
    return a;
}
#define SWZ128(b) ((b) ^ (((b) >> 3) & 0x70))
#define CP_ASYNC16(dst, src) \
    asm volatile("cp.async.cg.shared.global [%0], [%1], 16;" :: "r"(dst), "l"(src) : "memory")
#define CP_COMMIT  asm volatile("cp.async.commit_group;" ::: "memory")
#define CP_WAIT0   asm volatile("cp.async.wait_group 0;" ::: "memory")
#define CP_WAIT1   asm volatile("cp.async.wait_group 1;" ::: "memory")

// classic multi-block barrier: all 148 CTAs resident by construction
__device__ __forceinline__ void grid_bar() {
    __syncthreads();
    if (threadIdx.x == 0) {
        __threadfence();
        int gen = *(volatile int*)&g_bar_gen;
        if (atomicAdd(&g_bar_cnt, 1) == NBLK - 1) {
            g_bar_cnt = 0;
            __threadfence();
            atomicExch(&g_bar_gen, gen + 1);
        } else {
            while (*(volatile int*)&g_bar_gen == gen) { }
            __threadfence();
        }
    }
    __syncthreads();
}

#if USE_TCGEN05
__device__ __forceinline__ uint32_t elect_one() {
    uint32_t p;
    asm volatile("{ .reg .pred p; elect.sync _|p, 0xFFFFFFFF; selp.b32 %0, 1, 0, p; }" : "=r"(p));
    return p;
}
#define MBAR_INIT(a, c) asm volatile("mbarrier.init.shared.b64 [%0], %1;" :: "r"(a), "r"(c) : "memory")
#define MBAR_WAIT(a, ph) do { \
    uint32_t _m = (a); uint32_t _p = (ph); uint32_t _d; \
    asm volatile("{ .reg .pred p; mbarrier.try_wait.parity.acquire.cta.shared::cta.b64 p, [%1], %2; selp.b32 %0,1,0,p; }" \
        : "=r"(_d) : "r"(_m), "r"(_p) : "memory"); \
    if (!_d) { \
        asm volatile("{ .reg .pred P1; WL_%=: mbarrier.try_wait.parity.acquire.cta.shared::cta.b64 P1, [%0], %1, 0x989680; @P1 bra.uni WD_%=; bra.uni WL_%=; WD_%=: }" \
            :: "r"(_m), "r"(_p) : "memory"); \
    } } while (0)

static constexpr uint64_t DESC_BASE =
    (uint64_t(2) << 61) | (uint64_t(1) << 46) | (uint64_t(64) << 32) | (uint64_t(1) << 16);
#define MK_DESC(addr) (DESC_BASE | ((uint64_t)((addr) >> 4) & 0x3FFF))

static constexpr uint32_t IDESC = (1u << 4) | (1u << 7) | (1u << 10) | ((256u / 8) << 17) | ((128u / 16) << 24);

__device__ __forceinline__ void mma_f16_ss(uint32_t d, uint64_t ad, uint64_t bd, uint32_t idesc, bool acc) {
    uint32_t en = acc ? 1u : 0u, z = 0;
    asm volatile(
        "{ .reg .pred p; setp.ne.u32 p, %5, 0;\n\t"
        "tcgen05.mma.cta_group::1.kind::f16 [%0], %1, %2, %3, {%4, %4, %4, %4}, p; }"
        :: "r"(d), "l"(ad), "l"(bd), "r"(idesc), "r"(z), "r"(en) : "memory");
}
#endif

#define PAD_STRIDE 144
#define FA_BYTES  (128 * PAD_STRIDE)
#define FB_BYTES  (256 * PAD_STRIDE)
#define SMEM_NEED (1024 + 1024 + 2 * FA_BYTES + 2 * FB_BYTES)

// ---------------- GEMM phase (device fn): compensated dual GEMM + LN fused ---
template <int NCH, bool L0MODE>
__device__ void gemm_phase(char* smp, uint32_t sb, uint32_t tmem,
                           int tid, int wid, int lid, int m0,
                           const __nv_bfloat16* __restrict__ Wp,
                           const float* __restrict__ bi, const float* __restrict__ bo,
                           const float* __restrict__ lg, const float* __restrict__ lb,
                           int outbuf, int* ph) {
    const int segA[6] = {0, 0, 1, 2, 2, 3};
    const int ASTR = L0MODE ? 192 : 256;
    const int BSTR = L0MODE ? 192 : 256;
#if USE_TCGEN05
    const uint32_t aoff[2] = {1024u, 1024u + 128 * 128};
    const uint32_t boff[2] = {1024u + 2 * 128 * 128, 1024u + 2 * 128 * 128 + 256 * 128};
    float* sbias = (float*)(smp + 1024u + 2 * 128 * 128 + 2 * 256 * 128);
    float* sgam  = sbias + 256;
    float* sbet  = sgam + 256;
    sbias[tid] = bi[tid] + bo[tid];
    sgam[tid] = lg[tid];
    sbet[tid] = lb[tid];
    __syncthreads();

    int arowi[4], acol[4], adst[4], browi[8], bcol[8], bdst[8];
#pragma unroll
    for (int u = 0; u < 4; u++) {
        int idx = u * 256 + tid;
        arowi[u] = idx >> 3;
        int q = idx & 7;
        acol[u] = q * 8;
        adst[u] = SWZ128(arowi[u] * 128 + q * 16);
    }
#pragma unroll
    for (int u = 0; u < 8; u++) {
        int idx = u * 256 + tid;
        browi[u] = idx >> 3;
        int q = idx & 7;
        bcol[u] = q * 8;
        bdst[u] = SWZ128(browi[u] * 128 + q * 16);
    }

    auto issue_chunk = [&](int ck) {
        const __nv_bfloat16* Ag;
        const __nv_bfloat16* Bg;
        int koff;
        if (L0MODE) {
            Ag = g_A0 + (size_t)m0 * ASTR;
            Bg = Wp;
            koff = ck * 64;
        } else {
            int sg = ck >> 2, c = ck & 3;
            Ag = g_Abf[segA[sg]] + (size_t)m0 * ASTR;
            Bg = Wp + (size_t)sg * DD * DD;
            koff = c * 64;
        }
        int buf = ck & 1;
#pragma unroll
        for (int u = 0; u < 4; u++)
            CP_ASYNC16(sb + aoff[buf] + adst[u], Ag + (size_t)arowi[u] * ASTR + acol[u] + koff);
#pragma unroll
        for (int u = 0; u < 8; u++)
            CP_ASYNC16(sb + boff[buf] + bdst[u], Bg + (size_t)browi[u] * BSTR + bcol[u] + koff);
        CP_COMMIT;
    };

    issue_chunk(0);
    for (int chunk = 0; chunk < NCH; chunk++) {
        int buf = chunk & 1;
        if (chunk + 1 < NCH) {
            int nbuf = (chunk + 1) & 1;
            if (chunk >= 1) {
                if (nbuf == 0) { MBAR_WAIT(sb + 8, ph[0]); ph[0] ^= 1; }
                else           { MBAR_WAIT(sb + 16, ph[1]); ph[1] ^= 1; }
            }
            issue_chunk(chunk + 1);
            CP_WAIT1;
        } else {
            CP_WAIT0;
        }
        __syncthreads();
        if (wid == 0) {
            asm volatile("fence.proxy.async.shared::cta;" ::: "memory");
            if (elect_one()) {
                uint64_t ad = MK_DESC(sb + aoff[buf]);
                uint64_t bd = MK_DESC(sb + boff[buf]);
#pragma unroll
                for (int st = 0; st < 4; st++)
                    mma_f16_ss(tmem, ad + st * 2, bd + st * 2, IDESC, !(chunk == 0 && st == 0));
                asm volatile(
                    "tcgen05.commit.cta_group::1.mbarrier::arrive::one.shared::cluster.b64 [%0];"
                    :: "r"(sb + 8 + buf * 8) : "memory");
            }
        }
        __syncthreads();
    }
    MBAR_WAIT(sb + 8, ph[0]);
    MBAR_WAIT(sb + 16, ph[1]);
    ph[0] ^= 1; ph[1] ^= 1;
    asm volatile("tcgen05.fence::after_thread_sync;" ::: "memory");
    __syncthreads();

    if (wid < 4) {
        int row = m0 + wid * 32 + lid;
        float sum = 0.f, sq = 0.f;
        uint32_t r[32];
        for (int cb = 0; cb < 8; cb++) {
            asm volatile(
                "tcgen05.ld.sync.aligned.32x32b.x32.b32 "
                "{%0,%1,%2,%3,%4,%5,%6,%7,%8,%9,%10,%11,%12,%13,%14,%15,"
                "%16,%17,%18,%19,%20,%21,%22,%23,%24,%25,%26,%27,%28,%29,%30,%31}, [%32];"
                : "=r"(r[0]), "=r"(r[1]), "=r"(r[2]), "=r"(r[3]), "=r"(r[4]), "=r"(r[5]), "=r"(r[6]), "=r"(r[7]),
                  "=r"(r[8]), "=r"(r[9]), "=r"(r[10]), "=r"(r[11]), "=r"(r[12]), "=r"(r[13]), "=r"(r[14]), "=r"(r[15]),
                  "=r"(r[16]), "=r"(r[17]), "=r"(r[18]), "=r"(r[19]), "=r"(r[20]), "=r"(r[21]), "=r"(r[22]), "=r"(r[23]),
                  "=r"(r[24]), "=r"(r[25]), "=r"(r[26]), "=r"(r[27]), "=r"(r[28]), "=r"(r[29]), "=r"(r[30]), "=r"(r[31])
                : "r"(tmem + cb * 32));
            asm volatile("tcgen05.wait::ld.sync.aligned;" ::: "memory");
#pragma unroll
            for (int j = 0; j < 32; j++) {
                int nn = cb * 32 + j;
                float v = __uint_as_float(r[j]) + sbias[nn];
                sum += v; sq += v * v;
            }
        }
        float mean = sum * (1.f / DD);
        float var = sq * (1.f / DD) - mean * mean;
        float rstd = rsqrtf(var + 1e-5f);
        float* __restrict__ Hout = g_H[outbuf];
        for (int cb = 0; cb < 8; cb++) {
            asm volatile(
                "tcgen05.ld.sync.aligned.32x32b.x32.b32 "
                "{%0,%1,%2,%3,%4,%5,%6,%7,%8,%9,%10,%11,%12,%13,%14,%15,"
                "%16,%17,%18,%19,%20,%21,%22,%23,%24,%25,%26,%27,%28,%29,%30,%31}, [%32];"
                : "=r"(r[0]), "=r"(r[1]), "=r"(r[2]), "=r"(r[3]), "=r"(r[4]), "=r"(r[5]), "=r"(r[6]), "=r"(r[7]),
                  "=r"(r[8]), "=r"(r[9]), "=r"(r[10]), "=r"(r[11]), "=r"(r[12]), "=r"(r[13]), "=r"(r[14]), "=r"(r[15]),
                  "=r"(r[16]), "=r"(r[17]), "=r"(r[18]), "=r"(r[19]), "=r"(r[20]), "=r"(r[21]), "=r"(r[22]), "=r"(r[23]),
                  "=r"(r[24]), "=r"(r[25]), "=r"(r[26]), "=r"(r[27]), "=r"(r[28]), "=r"(r[29]), "=r"(r[30]), "=r"(r[31])
                : "r"(tmem + cb * 32));
            asm volatile("tcgen05.wait::ld.sync.aligned;" ::: "memory");
#pragma unroll
            for (int j = 0; j < 32; j++) {
                int nn = cb * 32 + j;
                float v = __uint_as_float(r[j]) + sbias[nn];
                float y = (v - mean) * rstd * sgam[nn] + sbet[nn];
                Hout[(size_t)row * DD + nn] = y > 0.f ? y : 0.f;
            }
        }
    }
    __syncthreads();
#else
    // fallback: mma.sync path (plain sm_103 image; structure-compatible)
    __shared__ float sdsum[128];
    __shared__ float sdsq[128];
    const uint32_t faoff[2] = {1024u, 1024u + FA_BYTES};
    const uint32_t fboff[2] = {1024u + 2 * FA_BYTES, 1024u + 2 * FA_BYTES + FB_BYTES};
    int gid = lid >> 2, t4 = lid & 3;
    int wm = wid >> 1, wn = wid & 1;
    int mrow = wm * 32, ncol = wn * 128;
    float acc[2][16][4];
#pragma unroll
    for (int i = 0; i < 2; i++)
#pragma unroll
        for (int j = 0; j < 16; j++)
#pragma unroll
            for (int q = 0; q < 4; q++) acc[i][j][q] = 0.f;
    for (int chunk = 0; chunk < NCH; chunk++) {
        const __nv_bfloat16* Ag;
        const __nv_bfloat16* Bg;
        int koff;
        if (L0MODE) { Ag = g_A0; Bg = Wp; koff = chunk * 64; }
        else {
            int sg = chunk >> 2, c = chunk & 3;
            Ag = g_Abf[segA[sg]];
            Bg = Wp + (size_t)sg * DD * DD;
            koff = c * 64;
        }
        int buf = chunk & 1;
        __syncthreads();
#pragma unroll
        for (int u = 0; u < 4; u++) {
            int idx = u * 256 + tid;
            int row = idx >> 3, q = idx & 7;
            uint4 v = *(const uint4*)(Ag + (size_t)(m0 + row) * ASTR + koff + q * 8);
            *(uint4*)(smp + faoff[buf] + row * PAD_STRIDE + q * 16) = v;
        }
#pragma unroll
        for (int u = 0; u < 8; u++) {
            int idx = u * 256 + tid;
            int row = idx >> 3, q = idx & 7;
            uint4 v = *(const uint4*)(Bg + (size_t)row * BSTR + koff + q * 8);
            *(uint4*)(smp + fboff[buf] + row * PAD_STRIDE + q * 16) = v;
        }
        __syncthreads();
        const char* ab = smp + faoff[buf];
        const char* bb = smp + fboff[buf];
#pragma unroll
        for (int ks = 0; ks < 4; ks++) {
            int kb = ks * 32;
            uint32_t a[2][4];
#pragma unroll
            for (int ma = 0; ma < 2; ma++) {
                int r0 = mrow + ma * 16 + gid;
                a[ma][0] = *(const uint32_t*)(ab + r0 * PAD_STRIDE + kb + t4 * 4);
                a[ma][1] = *(const uint32_t*)(ab + (r0 + 8) * PAD_STRIDE + kb + t4 * 4);
                a[ma][2] = *(const uint32_t*)(ab + r0 * PAD_STRIDE + kb + 16 + t4 * 4);
                a[ma][3] = *(const uint32_t*)(ab + (r0 + 8) * PAD_STRIDE + kb + 16 + t4 * 4);
            }
#pragma unroll
            for (int nb = 0; nb < 16; nb++) {
                int cc = ncol + nb * 8 + gid;
                uint32_t b0 = *(const uint32_t*)(bb + cc * PAD_STRIDE + kb + t4 * 4);
                uint32_t b1 = *(const uint32_t*)(bb + cc * PAD_STRIDE + kb + 16 + t4 * 4);
#pragma unroll
                for (int ma = 0; ma < 2; ma++) {
                    asm volatile(
                        "mma.sync.aligned.m16n8k16.row.col.f32.bf16.bf16.f32 "
                        "{%0,%1,%2,%3}, {%4,%5,%6,%7}, {%8,%9}, {%0,%1,%2,%3};"
                        : "+f"(acc[ma][nb][0]), "+f"(acc[ma][nb][1]),
                          "+f"(acc[ma][nb][2]), "+f"(acc[ma][nb][3])
                        : "r"(a[ma][0]), "r"(a[ma][1]), "r"(a[ma][2]), "r"(a[ma][3]),
                          "r"(b0), "r"(b1));
                }
            }
        }
    }
    __syncthreads();
    if (tid < 128) { sdsum[tid] = 0.f; sdsq[tid] = 0.f; }
    __syncthreads();
    float* __restrict__ Hout = g_H[outbuf];
#pragma unroll
    for (int ma = 0; ma < 2; ma++) {
#pragma unroll
        for (int nb = 0; nb < 16; nb++) {
#pragma unroll
            for (int q = 0; q < 4; q++) {
                int row = mrow + ma * 16 + gid + ((q >= 2) ? 8 : 0);
                int col = ncol + nb * 8 + t4 * 2 + (q & 1);
                float v = acc[ma][nb][q] + __ldg(&bi[col]) + __ldg(&bo[col]);
                Hout[(size_t)(m0 + row) * DD + col] = v;
                atomicAdd(&sdsum[row], v);
                atomicAdd(&sdsq[row], v * v);
            }
        }
    }
    __syncthreads();
    for (int r = wid; r < 128; r += 8) {
        float mean = sdsum[r] * (1.f / DD);
        float var = sdsq[r] * (1.f / DD) - mean * mean;
        float rstd = rsqrtf(var + 1e-5f);
#pragma unroll
        for (int u = 0; u < 8; u++) {
            int col = u * 32 + lid;
            float v = Hout[(size_t)(m0 + r) * DD + col];
            float y = (v - mean) * rstd * __ldg(&lg[col]) + __ldg(&lb[col]);
            Hout[(size_t)(m0 + r) * DD + col] = y > 0.f ? y : 0.f;
        }
    }
    __syncthreads();
#endif
}

// ---------------- the persistent mega-kernel --------------------------------
__global__ __launch_bounds__(256, 1) void k_mega(
    const float* __restrict__ x, const int* __restrict__ src, const int* __restrict__ dst,
    const void* __restrict__ msk, const float* __restrict__ s,
    const float* __restrict__ Wi0, const float* __restrict__ Wo0,
    const float* __restrict__ bi0, const float* __restrict__ bo0,
    const float* __restrict__ Wi, const float* __restrict__ Wo,
    const float* __restrict__ bi, const float* __restrict__ bo,
    const float* __restrict__ lg, const float* __restrict__ lb,
    const float* __restrict__ fg, const float* __restrict__ fb,
    const __nv_bfloat16* __restrict__ wp, const __nv_bfloat16* __restrict__ w0p,
    float* __restrict__ emb, float* __restrict__ fmask, float* __restrict__ regout)
{
    extern __shared__ char smem[];
    uint32_t raw = smem_u32(smem);
    uint32_t sb = (raw + 1023u) & ~1023u;
    char* smp = smem + (sb - raw);
    int tid = threadIdx.x, wid = tid >> 5, lid = tid & 31;
    int bx = blockIdx.x;
    __shared__ int sdeg[NSLC];

    uint32_t tmem = 0;
#if USE_TCGEN05
    if (wid == 0) {
        asm volatile("tcgen05.alloc.cta_group::1.sync.aligned.shared::cta.b32 [%0], %1;"
                     :: "r"(sb), "r"(256u) : "memory");
    }
    if (tid == 0) { MBAR_INIT(sb + 8, 1); MBAR_INIT(sb + 16, 1); }
    __syncthreads();
    asm volatile("ld.shared.b32 %0, [%1];" : "=r"(tmem) : "r"(sb));
#endif

    // ---- PHASE 1: setup (frag, x pad, weight prep, degree, mask detect) ----
    for (int idx = bx * 256 + tid; idx < NN * 32; idx += NBLK * 256) {
        if (idx < NN) {
            int f = 0;
#pragma unroll
            for (int k = 0; k < KF; k++)
                if (s[idx * KF + k] > 0.5f) f = k;
            g_frag[idx] = f;
        }
        {
            int n = idx >> 5, k = idx & 31;
            g_x32[idx] = (k < DIN) ? __ldg(&x[n * DIN + k]) : 0.f;
        }
        if (idx < 3 * DD * DD) {
            int l = idx / (DD * DD);
            int r = idx - l * DD * DD;
            int k = r / DD;
            int n = r - k * DD;
            float wi = Wi[idx], wo = Wo[idx];
            __nv_bfloat16 wih = __float2bfloat16(wi);
            __nv_bfloat16 wil = __float2bfloat16(wi - __bfloat162float(wih));
            __nv_bfloat16 woh = __float2bfloat16(wo);
            __nv_bfloat16 wol = __float2bfloat16(wo - __bfloat162float(woh));
            size_t base = (size_t)l * 6 * DD * DD + (size_t)n * DD + k;
            g_Wp[base + 0 * DD * DD] = wih;
            g_Wp[base + 1 * DD * DD] = wil;
            g_Wp[base + 2 * DD * DD] = wih;
            g_Wp[base + 3 * DD * DD] = woh;
            g_Wp[base + 4 * DD * DD] = wol;
            g_Wp[base + 5 * DD * DD] = woh;
        }
        if (idx < DD * DIN) {
            int n = idx / DIN;
            int k = idx - n * DIN;
            float wi = Wi0[k * DD + n], wo = Wo0[k * DD + n];
            __nv_bfloat16 wih = __float2bfloat16(wi);
            __nv_bfloat16 wil = __float2bfloat16(wi - __bfloat162float(wih));
            __nv_bfloat16 woh = __float2bfloat16(wo);
            __nv_bfloat16 wol = __float2bfloat16(wo - __bfloat162float(woh));
            __nv_bfloat16* W0 = g_W0p + n * 192;
            W0[0 * 32 + k] = wih;
            W0[1 * 32 + k] = wil;
            W0[2 * 32 + k] = wih;
            W0[3 * 32 + k] = woh;
            W0[4 * 32 + k] = wol;
            W0[5 * 32 + k] = woh;
        }
        if (idx < 1024) {
            const unsigned char* mb = (const unsigned char*)msk;
            int i4 = idx * 4;
            int nz = (int)mb[i4 + 1] | (int)mb[i4 + 2] | (int)mb[i4 + 3];
            if (nz) atomicOr(&g_mask_nz, 1);   // idempotent: replay-safe
        }
        if (idx < NE) atomicAdd(&g_deg[dst[idx]], 1);
    }
    grid_bar();

    // ---- PHASE 2: parallel scan (slices -> partials -> offsets) ----
    int nbase = bx * NSLC;
    if (tid < NSLC) {
        int n = nbase + tid;
        int v = 0;
        if (n < NN) {
            v = g_deg[n];
            g_dinv[n] = rsqrtf((float)(v > 0 ? v : 1));
            g_deg[n] = 0;
            g_cur[n] = 0;
        }
        sdeg[tid] = v;
    }
    __syncthreads();
    if (tid == 0) {
        int tot = 0;
#pragma unroll 1
        for (int i = 0; i < NSLC; i++) { int v = sdeg[i]; sdeg[i] = tot; tot += v; }
        g_part[bx] = tot;
    }
    __syncthreads();
    grid_bar();
    if (bx == 0 && tid == 0) {
        int acc = 0;
#pragma unroll 1
        for (int i = 0; i < NBLK; i++) { g_partoff[i] = acc; acc += g_part[i]; }
        g_off[NN] = acc;
    }
    grid_bar();
    if (tid < NSLC) {
        int n = nbase + tid;
        if (n < NN) g_off[n] = g_partoff[bx] + sdeg[tid];
    }
    grid_bar();

    // ---- PHASE 3: CSR scatter ----
    {
        int mask_int = (*(volatile int*)&g_mask_nz == 0);
        for (int e = bx * 256 + tid; e < NE; e += NBLK * 256) {
            int u = src[e], v = dst[e];
            int mb;
            if (mask_int) mb = (((const int*)msk)[e] != 0) ? 1 : 0;
            else          mb = (((const unsigned char*)msk)[e] != 0) ? 1 : 0;
            int p = g_off[v] + atomicAdd(&g_cur[v], 1);
            g_csrw[p] = make_int2((u << 1) | mb, __float_as_int(g_dinv[u] * g_dinv[v]));
        }
    }
    grid_bar();

    // ---- PHASE 4: layer-0 aggregate (warp per node) ----
    for (int n = bx * 8 + wid; n < NN; n += NBLK * 8) {
        int beg = g_off[n], end = g_off[n + 1];
        float ai = 0.f, ao = 0.f;
        int j = beg;
        if (j < end && (j & 1)) {
            int2 e = g_csrw[j];
            float v = __ldg(&g_x32[(e.x >> 1) * 32 + lid]);
            float w = __int_as_float(e.y);
            float wi = (e.x & 1) ? w : 0.f, wo = (e.x & 1) ? 0.f : w;
            ai = fmaf(wi, v, ai); ao = fmaf(wo, v, ao);
            j++;
        }
        for (; j + 2 <= end; j += 2) {
            int4 p = *(const int4*)&g_csrw[j];
            float v0 = __ldg(&g_x32[(p.x >> 1) * 32 + lid]);
            float v1 = __ldg(&g_x32[(p.z >> 1) * 32 + lid]);
            float w0 = __int_as_float(p.y), w1 = __int_as_float(p.w);
            float wi0 = (p.x & 1) ? w0 : 0.f, wo0 = (p.x & 1) ? 0.f : w0;
            float wi1 = (p.z & 1) ? w1 : 0.f, wo1 = (p.z & 1) ? 0.f : w1;
            ai = fmaf(wi0, v0, ai); ao = fmaf(wo0, v0, ao);
            ai = fmaf(wi1, v1, ai); ao = fmaf(wo1, v1, ao);
        }
        for (; j < end; j++) {
            int2 e = g_csrw[j];
            float v = __ldg(&g_x32[(e.x >> 1) * 32 + lid]);
            float w = __int_as_float(e.y);
            float wi = (e.x & 1) ? w : 0.f, wo = (e.x & 1) ? 0.f : w;
            ai = fmaf(wi, v, ai); ao = fmaf(wo, v, ao);
        }
        __nv_bfloat16 aih = __float2bfloat16(ai);
        __nv_bfloat16 ail = __float2bfloat16(ai - __bfloat162float(aih));
        __nv_bfloat16 aoh = __float2bfloat16(ao);
        __nv_bfloat16 aol = __float2bfloat16(ao - __bfloat162float(aoh));
        __nv_bfloat16* A0 = g_A0 + n * 192;
        A0[0 * 32 + lid] = aih;
        A0[1 * 32 + lid] = aih;
        A0[2 * 32 + lid] = ail;
        A0[3 * 32 + lid] = aoh;
        A0[4 * 32 + lid] = aoh;
        A0[5 * 32 + lid] = aol;
    }
    grid_bar();

    // ---- PHASE 5: layer-0 GEMM ----
    int ph[2] = {0, 0};
    if (bx < NN / 128)
        gemm_phase<3, true>(smp, sb, tmem, tid, wid, lid, bx * 128,
                            w0p, bi0, bo0, lg, lb, 0, ph);
    __threadfence();
    grid_bar();

    // ---- PHASE 6: 3 x (SpMM ; GEMM) ----
    int cur = 0;
    for (int l = 0; l < 3; l++) {
        const float4* __restrict__ H4 = (const float4*)g_H[cur];
        int grp = tid >> 6;
        int c4 = tid & 63;
        for (int n = bx * 4 + grp; n < NN; n += NBLK * 4) {
            int beg = g_off[n], end = g_off[n + 1];
            float4 ai = make_float4(0.f, 0.f, 0.f, 0.f);
            float4 ao = make_float4(0.f, 0.f, 0.f, 0.f);
            int j = beg;
            if (j < end && (j & 1)) {
                int2 e = g_csrw[j];
                float4 v = __ldg(&H4[(size_t)(e.x >> 1) * 64 + c4]);
                float w = __int_as_float(e.y);
                float wi = (e.x & 1) ? w : 0.f, wo = (e.x & 1) ? 0.f : w;
                ai.x = fmaf(wi, v.x, ai.x); ai.y = fmaf(wi, v.y, ai.y);
                ai.z = fmaf(wi, v.z, ai.z); ai.w = fmaf(wi, v.w, ai.w);
                ao.x = fmaf(wo, v.x, ao.x); ao.y = fmaf(wo, v.y, ao.y);
                ao.z = fmaf(wo, v.z, ao.z); ao.w = fmaf(wo, v.w, ao.w);
                j++;
            }
            for (; j + 4 <= end; j += 4) {
                int4 p0 = *(const int4*)&g_csrw[j];
                int4 p1 = *(const int4*)&g_csrw[j + 2];
                float4 v0 = __ldg(&H4[(size_t)(p0.x >> 1) * 64 + c4]);
                float4 v1 = __ldg(&H4[(size_t)(p0.z >> 1) * 64 + c4]);
                float4 v2 = __ldg(&H4[(size_t)(p1.x >> 1) * 64 + c4]);
                float4 v3 = __ldg(&H4[(size_t)(p1.z >> 1) * 64 + c4]);
                float w0 = __int_as_float(p0.y), w1 = __int_as_float(p0.w);
                float w2 = __int_as_float(p1.y), w3 = __int_as_float(p1.w);
                float wi0 = (p0.x & 1) ? w0 : 0.f, wo0 = (p0.x & 1) ? 0.f : w0;
                float wi1 = (p0.z & 1) ? w1 : 0.f, wo1 = (p0.z & 1) ? 0.f : w1;
                float wi2 = (p1.x & 1) ? w2 : 0.f, wo2 = (p1.x & 1) ? 0.f : w2;
                float wi3 = (p1.z & 1) ? w3 : 0.f, wo3 = (p1.z & 1) ? 0.f : w3;
                ai.x = fmaf(wi0, v0.x, ai.x); ai.y = fmaf(wi0, v0.y, ai.y);
                ai.z = fmaf(wi0, v0.z, ai.z); ai.w = fmaf(wi0, v0.w, ai.w);
                ao.x = fmaf(wo0, v0.x, ao.x); ao.y = fmaf(wo0, v0.y, ao.y);
                ao.z = fmaf(wo0, v0.z, ao.z); ao.w = fmaf(wo0, v0.w, ao.w);
                ai.x = fmaf(wi1, v1.x, ai.x); ai.y = fmaf(wi1, v1.y, ai.y);
                ai.z = fmaf(wi1, v1.z, ai.z); ai.w = fmaf(wi1, v1.w, ai.w);
                ao.x = fmaf(wo1, v1.x, ao.x); ao.y = fmaf(wo1, v1.y, ao.y);
                ao.z = fmaf(wo1, v1.z, ao.z); ao.w = fmaf(wo1, v1.w, ao.w);
                ai.x = fmaf(wi2, v2.x, ai.x); ai.y = fmaf(wi2, v2.y, ai.y);
                ai.z = fmaf(wi2, v2.z, ai.z); ai.w = fmaf(wi2, v2.w, ai.w);
                ao.x = fmaf(wo2, v2.x, ao.x); ao.y = fmaf(wo2, v2.y, ao.y);
                ao.z = fmaf(wo2, v2.z, ao.z); ao.w = fmaf(wo2, v2.w, ao.w);
                ai.x = fmaf(wi3, v3.x, ai.x); ai.y = fmaf(wi3, v3.y, ai.y);
                ai.z = fmaf(wi3, v3.z, ai.z); ai.w = fmaf(wi3, v3.w, ai.w);
                ao.x = fmaf(wo3, v3.x, ao.x); ao.y = fmaf(wo3, v3.y, ao.y);
                ao.z = fmaf(wo3, v3.z, ao.z); ao.w = fmaf(wo3, v3.w, ao.w);
            }
            for (; j < end; j++) {
                int2 e = g_csrw[j];
                float4 v = __ldg(&H4[(size_t)(e.x >> 1) * 64 + c4]);
                float w = __int_as_float(e.y);
                float wi = (e.x & 1) ? w : 0.f, wo = (e.x & 1) ? 0.f : w;
                ai.x = fmaf(wi, v.x, ai.x); ai.y = fmaf(wi, v.y, ai.y);
                ai.z = fmaf(wi, v.z, ai.z); ai.w = fmaf(wi, v.w, ai.w);
                ao.x = fmaf(wo, v.x, ao.x); ao.y = fmaf(wo, v.y, ao.y);
                ao.z = fmaf(wo, v.z, ao.z); ao.w = fmaf(wo, v.w, ao.w);
            }
            int ou = n * 64 + c4;
            union { __nv_bfloat162 h2[2]; uint2 u; } pk;
            __nv_bfloat16 h0, h1, h2b, h3;
            h0 = __float2bfloat16(ai.x); h1 = __float2bfloat16(ai.y);
            h2b = __float2bfloat16(ai.z); h3 = __float2bfloat16(ai.w);
            pk.h2[0] = __nv_bfloat162(h0, h1); pk.h2[1] = __nv_bfloat162(h2b, h3);
            ((uint2*)g_Abf[0])[ou] = pk.u;
            pk.h2[0] = __nv_bfloat162(__float2bfloat16(ai.x - __bfloat162float(h0)),
                                      __float2bfloat16(ai.y - __bfloat162float(h1)));
            pk.h2[1] = __nv_bfloat162(__float2bfloat16(ai.z - __bfloat162float(h2b)),
                                      __float2bfloat16(ai.w - __bfloat162float(h3)));
            ((uint2*)g_Abf[1])[ou] = pk.u;
            h0 = __float2bfloat16(ao.x); h1 = __float2bfloat16(ao.y);
            h2b = __float2bfloat16(ao.z); h3 = __float2bfloat16(ao.w);
            pk.h2[0] = __nv_bfloat162(h0, h1); pk.h2[1] = __nv_bfloat162(h2b, h3);
            ((uint2*)g_Abf[2])[ou] = pk.u;
            pk.h2[0] = __nv_bfloat162(__float2bfloat16(ao.x - __bfloat162float(h0)),
                                      __float2bfloat16(ao.y - __bfloat162float(h1)));
            pk.h2[1] = __nv_bfloat162(__float2bfloat16(ao.z - __bfloat162float(h2b)),
                                      __float2bfloat16(ao.w - __bfloat162float(h3)));
            ((uint2*)g_Abf[3])[ou] = pk.u;
        }
        __threadfence();
        grid_bar();

        if (bx < NN / 128)
            gemm_phase<24, false>(smp, sb, tmem, tid, wid, lid, bx * 128,
                                  wp + (size_t)l * 6 * DD * DD,
                                  bi + l * DD, bo + l * DD,
                                  lg + (l + 1) * DD, lb + (l + 1) * DD, 1 - cur, ph);
        __threadfence();
        grid_bar();
        cur = 1 - cur;
    }

    // ---- PHASE 7: fragment pooling + LN + mask; reg loss on block 64 ----
    if (bx < BBG) {
        const float* __restrict__ H = g_H[cur];
        float* sacc = (float*)(smp + 1024);          // 16KB, reuses GEMM buffers
        __shared__ int sfrag[NPGX];
        __shared__ int scnt[KF];
        __shared__ float w1[8], w2[8];
#pragma unroll
        for (int kf = 0; kf < KF; kf++) sacc[kf * DD + tid] = 0.f;
        if (tid < NPGX) sfrag[tid] = g_frag[bx * NPGX + tid];
        __syncthreads();
        int base = bx * NPGX;
        int cnt_local = 0;
        for (int p = 0; p < NPGX; p++) {
            int f = sfrag[p];
            float v = H[(size_t)(base + p) * DD + tid];
            sacc[f * DD + tid] += v;
            if (tid == f) cnt_local++;
        }
        if (tid < KF) scnt[tid] = cnt_local;
        __syncthreads();
        for (int kf = 0; kf < KF; kf++) {
            float acc = sacc[kf * DD + tid];
            float s1 = acc, s2 = acc * acc;
#pragma unroll
            for (int o = 16; o > 0; o >>= 1) {
                s1 += __shfl_xor_sync(0xFFFFFFFFu, s1, o);
                s2 += __shfl_xor_sync(0xFFFFFFFFu, s2, o);
            }
            if (lid == 0) { w1[wid] = s1; w2[wid] = s2; }
            __syncthreads();
            float t1 = 0.f, t2 = 0.f;
#pragma unroll
            for (int i = 0; i < 8; i++) { t1 += w1[i]; t2 += w2[i]; }
            float m = t1 * (1.f / DD);
            float var = t2 * (1.f / DD) - m * m;
            float y = (acc - m) * rsqrtf(var + 1e-5f) * fg[tid] + fb[tid];
            emb[(size_t)(bx * KF + kf) * DD + tid] = y;
            if (tid == 0) fmask[bx * KF + kf] = (scnt[kf] > 0) ? 1.f : 0.f;
            __syncthreads();
        }
    } else if (bx == BBG) {
        __shared__ float r[256];
        float a = 0.f;
        for (int i = tid; i < DIN * DD; i += 256) a += fabsf(Wo0[i]);
        a += fabsf(bo0[tid]);
        for (int i = tid; i < 3 * DD * DD; i += 256) a += fabsf(Wo[i]);
        for (int i = tid; i < 3 * DD; i += 256) a += fabsf(bo[i]);
        r[tid] = a;
        __syncthreads();
        for (int o = 128; o > 0; o >>= 1) {
            if (tid < o) r[tid] += r[tid + o];
            __syncthreads();
        }
        if (tid == 0) regout[0] = r[0];
    }

#if USE_TCGEN05
    __syncthreads();
    if (wid == 0) {
        asm volatile("tcgen05.relinquish_alloc_permit.cta_group::1.sync.aligned;");
        asm volatile("tcgen05.dealloc.cta_group::1.sync.aligned.b32 %0, %1;" :: "r"(tmem), "r"(256u));
    }
#endif
}

// ---------------- launch ----------------
extern "C" void kernel_launch(void* const* d_in, const int* in_sizes, int n_in,
                              void* d_out, int out_size) {
    const float* x   = (const float*)d_in[0];
    const int*   ei  = (const int*)d_in[1];
    const void*  msk = d_in[2];
    const float* s   = (const float*)d_in[3];
    const float* Wi0 = (const float*)d_in[5];
    const float* Wo0 = (const float*)d_in[6];
    const float* bi0 = (const float*)d_in[7];
    const float* bo0 = (const float*)d_in[8];
    const float* Wi  = (const float*)d_in[9];
    const float* Wo  = (const float*)d_in[10];
    const float* bi  = (const float*)d_in[11];
    const float* bo  = (const float*)d_in[12];
    const float* lg  = (const float*)d_in[13];
    const float* lb  = (const float*)d_in[14];
    const float* fg  = (const float*)d_in[15];
    const float* fb  = (const float*)d_in[16];
    float* out = (float*)d_out;

    const int* src = ei;
    const int* dst = ei + NE;

    cudaFuncSetAttribute(k_mega, cudaFuncAttributeMaxDynamicSharedMemorySize, SMEM_NEED);

    __nv_bfloat16* wp_dev = nullptr;
    cudaGetSymbolAddress((void**)&wp_dev, g_Wp);
    __nv_bfloat16* w0p_dev = nullptr;
    cudaGetSymbolAddress((void**)&w0p_dev, g_W0p);

    k_mega<<<NBLK, 256, SMEM_NEED>>>(
        x, src, dst, msk, s, Wi0, Wo0, bi0, bo0, Wi, Wo, bi, bo, lg, lb, fg, fb,
        wp_dev, w0p_dev,
        out, out + BBG * KF * DD, out + BBG * KF * DD + BBG * KF);
}

// round 17
// speedup vs baseline: 1.8098x; 1.8098x over previous
#include <cuda_runtime.h>
#include <cuda_bf16.h>
#include <cstdint>

#define NN   10240
#define NE   320000
#define BBG  64
#define NPGX 160
#define KF   16
#define DIN  25
#define DD   256

#if defined(__CUDA_ARCH_FEAT_SM103_ALL) || defined(__CUDA_ARCH_FEAT_SM100_ALL)
#define USE_TCGEN05 1
#else
#define USE_TCGEN05 0
#endif

// ---------------- device scratch (static, allocation-free) ----------------
__device__ int   g_deg[NN];          // zero at load; reset by k_scan each run
__device__ int   g_cur[NN];          // reset by k_scan each run
__device__ int   g_off[NN + 1];
__device__ float g_dinv[NN];
__device__ __align__(16) int2  g_csrw[NE];   // {(src<<1)|mask, bitcast(norm)}
__device__ int   g_frag[NN];
__device__ int   g_mask_is_int;
__device__ __align__(16) float g_H[2][NN * DD];
__device__ __align__(16) float g_x32[NN * 32];   // x padded to 32 cols (25..31 zero)
// bf16 split SpMM outputs: 0=AGI_hi 1=AGI_lo 2=AGO_hi 3=AGO_lo
__device__ __align__(16) __nv_bfloat16 g_Abf[4][NN * DD];
// packed transposed weights: [3 layers][6 segs][256 n][256 k] bf16
__device__ __align__(16) __nv_bfloat16 g_Wp[3 * 6 * DD * DD];
// layer-0: interleaved A [NN][192] and W [256][192] (K pads stay zero)
__device__ __align__(16) __nv_bfloat16 g_A0[NN * 192];
__device__ __align__(16) __nv_bfloat16 g_W0p[DD * 192];

// ---------------- PTX helpers ----------------
__device__ __forceinline__ uint32_t smem_u32(const void* p) {
    uint32_t a;
    asm("{ .reg .u64 t; cvta.to.shared.u64 t, %1; cvt.u32.u64 %0, t; }" : "=r"(a) : "l"(p));
    return a;
}
__device__ __forceinline__ void pdl_wait() {
#if defined(__CUDA_ARCH__) && __CUDA_ARCH__ >= 900
    cudaGridDependencySynchronize();
#endif
}
#define SWZ128(b) ((b) ^ (((b) >> 3) & 0x70))
#define CP_ASYNC16(dst, src) \
    asm volatile("cp.async.cg.shared.global [%0], [%1], 16;" :: "r"(dst), "l"(src) : "memory")
#define CP_COMMIT  asm volatile("cp.async.commit_group;" ::: "memory")
#define CP_WAIT0   asm volatile("cp.async.wait_group 0;" ::: "memory")
#define CP_WAIT1   asm volatile("cp.async.wait_group 1;" ::: "memory")

#if USE_TCGEN05
__device__ __forceinline__ uint32_t elect_one() {
    uint32_t p;
    asm volatile("{ .reg .pred p; elect.sync _|p, 0xFFFFFFFF; selp.b32 %0, 1, 0, p; }" : "=r"(p));
    return p;
}
#define MBAR_INIT(a, c) asm volatile("mbarrier.init.shared.b64 [%0], %1;" :: "r"(a), "r"(c) : "memory")
#define MBAR_WAIT(a, ph) do { \
    uint32_t _m = (a); uint32_t _p = (ph); uint32_t _d; \
    asm volatile("{ .reg .pred p; mbarrier.try_wait.parity.acquire.cta.shared::cta.b64 p, [%1], %2; selp.b32 %0,1,0,p; }" \
        : "=r"(_d) : "r"(_m), "r"(_p) : "memory"); \
    if (!_d) { \
        asm volatile("{ .reg .pred P1; WL_%=: mbarrier.try_wait.parity.acquire.cta.shared::cta.b64 P1, [%0], %1, 0x989680; @P1 bra.uni WD_%=; bra.uni WL_%=; WD_%=: }" \
            :: "r"(_m), "r"(_p) : "memory"); \
    } } while (0)

static constexpr uint64_t DESC_BASE =
    (uint64_t(2) << 61) | (uint64_t(1) << 46) | (uint64_t(64) << 32) | (uint64_t(1) << 16);
#define MK_DESC(addr) (DESC_BASE | ((uint64_t)((addr) >> 4) & 0x3FFF))

static constexpr uint32_t IDESC = (1u << 4) | (1u << 7) | (1u << 10) | ((256u / 8) << 17) | ((128u / 16) << 24);

__device__ __forceinline__ void mma_f16_ss(uint32_t d, uint64_t ad, uint64_t bd, uint32_t idesc, bool acc) {
    uint32_t en = acc ? 1u : 0u, z = 0;
    asm volatile(
        "{ .reg .pred p; setp.ne.u32 p, %5, 0;\n\t"
        "tcgen05.mma.cta_group::1.kind::f16 [%0], %1, %2, %3, {%4, %4, %4, %4}, p; }"
        :: "r"(d), "l"(ad), "l"(bd), "r"(idesc), "r"(z), "r"(en) : "memory");
}
#endif

// ---------------- fused setup: frag + degree + weight prep + x pad ----------
__global__ void k_setup(const float* __restrict__ s, const int* __restrict__ dst,
                        const float* __restrict__ Wi, const float* __restrict__ Wo,
                        const float* __restrict__ Wi0, const float* __restrict__ Wo0,
                        const float* __restrict__ x) {
    int idx = blockIdx.x * blockDim.x + threadIdx.x;   // grid covers NN*32 (>= NE)
    if (idx < NN) {
        int f = 0;
#pragma unroll
        for (int k = 0; k < KF; k++)
            if (s[idx * KF + k] > 0.5f) f = k;
        g_frag[idx] = f;
    }
    if (idx < NN * 32) {
        int n = idx >> 5, k = idx & 31;
        g_x32[idx] = (k < DIN) ? __ldg(&x[n * DIN + k]) : 0.f;
    }
    if (idx < 3 * DD * DD) {
        int l = idx / (DD * DD);
        int r = idx - l * DD * DD;
        int k = r / DD;
        int n = r - k * DD;
        float wi = Wi[idx], wo = Wo[idx];
        __nv_bfloat16 wih = __float2bfloat16(wi);
        __nv_bfloat16 wil = __float2bfloat16(wi - __bfloat162float(wih));
        __nv_bfloat16 woh = __float2bfloat16(wo);
        __nv_bfloat16 wol = __float2bfloat16(wo - __bfloat162float(woh));
        size_t base = (size_t)l * 6 * DD * DD + (size_t)n * DD + k;
        g_Wp[base + 0 * DD * DD] = wih;
        g_Wp[base + 1 * DD * DD] = wil;
        g_Wp[base + 2 * DD * DD] = wih;
        g_Wp[base + 3 * DD * DD] = woh;
        g_Wp[base + 4 * DD * DD] = wol;
        g_Wp[base + 5 * DD * DD] = woh;
    }
    if (idx < DD * DIN) {
        int n = idx / DIN;
        int k = idx - n * DIN;
        float wi = Wi0[k * DD + n], wo = Wo0[k * DD + n];
        __nv_bfloat16 wih = __float2bfloat16(wi);
        __nv_bfloat16 wil = __float2bfloat16(wi - __bfloat162float(wih));
        __nv_bfloat16 woh = __float2bfloat16(wo);
        __nv_bfloat16 wol = __float2bfloat16(wo - __bfloat162float(woh));
        __nv_bfloat16* W0 = g_W0p + n * 192;
        W0[0 * 32 + k] = wih;
        W0[1 * 32 + k] = wil;
        W0[2 * 32 + k] = wih;
        W0[3 * 32 + k] = woh;
        W0[4 * 32 + k] = wol;
        W0[5 * 32 + k] = woh;
    }
    if (idx < NE) atomicAdd(&g_deg[dst[idx]], 1);
}

// Single-block scan: off/dinv from deg; resets deg & cur for next graph replay.
__global__ void k_scan(const unsigned char* __restrict__ maskb) {
    __shared__ int warp_tot[32];
    __shared__ int warp_pre[32];
    int t = threadIdx.x;
    int lane = t & 31, wd = t >> 5;
    {
        int idx = t * 4;
        int nz = (int)maskb[idx + 1] | (int)maskb[idx + 2] | (int)maskb[idx + 3];
        if (__syncthreads_or(nz)) { if (t == 0) g_mask_is_int = 0; }
        else                      { if (t == 0) g_mask_is_int = 1; }
    }
    int base = t * 10;
    int loc[10];
    int tot = 0;
#pragma unroll
    for (int i = 0; i < 10; i++) {
        int v = g_deg[base + i];
        g_dinv[base + i] = rsqrtf((float)(v > 0 ? v : 1));
        g_deg[base + i] = 0;
        g_cur[base + i] = 0;
        loc[i] = tot;
        tot += v;
    }
    int inc = tot;
#pragma unroll
    for (int o = 1; o < 32; o <<= 1) {
        int nv = __shfl_up_sync(0xFFFFFFFFu, inc, o);
        if (lane >= o) inc += nv;
    }
    if (lane == 31) warp_tot[wd] = inc;
    __syncthreads();
    if (wd == 0) {
        int v = warp_tot[lane];
        int iv = v;
#pragma unroll
        for (int o = 1; o < 32; o <<= 1) {
            int nv = __shfl_up_sync(0xFFFFFFFFu, iv, o);
            if (lane >= o) iv += nv;
        }
        warp_pre[lane] = iv - v;
    }
    __syncthreads();
    int texcl = inc - tot + warp_pre[wd];
#pragma unroll
    for (int i = 0; i < 10; i++)
        g_off[base + i] = texcl + loc[i];
    if (t == 1023) g_off[NN] = texcl + tot;
}

__global__ void k_csr(const int* __restrict__ src, const int* __restrict__ dst,
                      const void* __restrict__ maskp) {
    int e = blockIdx.x * blockDim.x + threadIdx.x;
    if (e >= NE) return;
    int u = src[e], v = dst[e];       // harness inputs: safe before pdl_wait
    pdl_wait();                        // g_off/g_dinv/g_mask_is_int from k_scan
    int mb;
    if (g_mask_is_int) mb = (((const int*)maskp)[e] != 0) ? 1 : 0;
    else               mb = (((const unsigned char*)maskp)[e] != 0) ? 1 : 0;
    int p = g_off[v] + atomicAdd(&g_cur[v], 1);
    g_csrw[p] = make_int2((u << 1) | mb, __float_as_int(g_dinv[u] * g_dinv[v]));
}

// ---------------- layer 0 aggregate: 1 warp/node 32-pad gather -> A0 splits --
__global__ void k_ag0() {
    int wd = threadIdx.x >> 5, lane = threadIdx.x & 31;
    int n = blockIdx.x * 8 + wd;
    pdl_wait();                        // g_csrw from k_csr
    int beg = g_off[n], end = g_off[n + 1];
    float ai = 0.f, ao = 0.f;
    int j = beg;
    if (j < end && (j & 1)) {
        int2 e = g_csrw[j];
        float v = __ldg(&g_x32[(e.x >> 1) * 32 + lane]);
        float w = __int_as_float(e.y);
        float wi = (e.x & 1) ? w : 0.f, wo = (e.x & 1) ? 0.f : w;
        ai = fmaf(wi, v, ai); ao = fmaf(wo, v, ao);
        j++;
    }
    for (; j + 4 <= end; j += 4) {
        int4 p0 = *(const int4*)&g_csrw[j];
        int4 p1 = *(const int4*)&g_csrw[j + 2];
        float v0 = __ldg(&g_x32[(p0.x >> 1) * 32 + lane]);
        float v1 = __ldg(&g_x32[(p0.z >> 1) * 32 + lane]);
        float v2 = __ldg(&g_x32[(p1.x >> 1) * 32 + lane]);
        float v3 = __ldg(&g_x32[(p1.z >> 1) * 32 + lane]);
        float w0 = __int_as_float(p0.y), w1 = __int_as_float(p0.w);
        float w2 = __int_as_float(p1.y), w3 = __int_as_float(p1.w);
        float wi0 = (p0.x & 1) ? w0 : 0.f, wo0 = (p0.x & 1) ? 0.f : w0;
        float wi1 = (p0.z & 1) ? w1 : 0.f, wo1 = (p0.z & 1) ? 0.f : w1;
        float wi2 = (p1.x & 1) ? w2 : 0.f, wo2 = (p1.x & 1) ? 0.f : w2;
        float wi3 = (p1.z & 1) ? w3 : 0.f, wo3 = (p1.z & 1) ? 0.f : w3;
        ai = fmaf(wi0, v0, ai); ao = fmaf(wo0, v0, ao);
        ai = fmaf(wi1, v1, ai); ao = fmaf(wo1, v1, ao);
        ai = fmaf(wi2, v2, ai); ao = fmaf(wo2, v2, ao);
        ai = fmaf(wi3, v3, ai); ao = fmaf(wo3, v3, ao);
    }
    for (; j < end; j++) {
        int2 e = g_csrw[j];
        float v = __ldg(&g_x32[(e.x >> 1) * 32 + lane]);
        float w = __int_as_float(e.y);
        float wi = (e.x & 1) ? w : 0.f, wo = (e.x & 1) ? 0.f : w;
        ai = fmaf(wi, v, ai); ao = fmaf(wo, v, ao);
    }
    __nv_bfloat16 aih = __float2bfloat16(ai);
    __nv_bfloat16 ail = __float2bfloat16(ai - __bfloat162float(aih));
    __nv_bfloat16 aoh = __float2bfloat16(ao);
    __nv_bfloat16 aol = __float2bfloat16(ao - __bfloat162float(aoh));
    __nv_bfloat16* A0 = g_A0 + n * 192;
    A0[0 * 32 + lane] = aih;
    A0[1 * 32 + lane] = aih;
    A0[2 * 32 + lane] = ail;
    A0[3 * 32 + lane] = aoh;
    A0[4 * 32 + lane] = aoh;
    A0[5 * 32 + lane] = aol;
}

// ---------------- GEMM: compensated dual GEMM + bias + LN + ReLU fused -------
// L0MODE: A = g_A0 [NN][192], B = g_W0p [256][192], NCH=3 chunks of K=64.
// layer:  A = g_Abf segments [NN][256], B = Wp segs [256][256], NCH=24.
// 2-stage cp.async pipeline; chunk-0 B prefetched BEFORE the PDL wait.
#define PAD_STRIDE 144
#define FA_BYTES  (128 * PAD_STRIDE)
#define FB_BYTES  (256 * PAD_STRIDE)
#define SMEM_NEED (1024 + 1024 + 2 * FA_BYTES + 2 * FB_BYTES)

template <int NCH, bool L0MODE>
__global__ __launch_bounds__(256, 1) void k_gemm_tc(
    const __nv_bfloat16* __restrict__ Wp,
    const float* __restrict__ bi, const float* __restrict__ bo,
    const float* __restrict__ lg, const float* __restrict__ lb,
    int outbuf)
{
    extern __shared__ char smem[];
    uint32_t raw = smem_u32(smem);
    uint32_t sb = (raw + 1023u) & ~1023u;
    int tid = threadIdx.x;
    int wid = tid >> 5, lid = tid & 31;
    int m0 = blockIdx.x * 128;
    const int segA[6] = {0, 0, 1, 2, 2, 3};
    const int ASTR = L0MODE ? 192 : 256;
    const int BSTR = L0MODE ? 192 : 256;

#if USE_TCGEN05
    const uint32_t aoff[2] = {1024u, 1024u + 128 * 128};
    const uint32_t boff[2] = {1024u + 2 * 128 * 128, 1024u + 2 * 128 * 128 + 256 * 128};
    char* smp = smem + (sb - raw);
    float* sbias = (float*)(smp + 1024u + 2 * 128 * 128 + 2 * 256 * 128);
    float* sgam  = sbias + 256;
    float* sbet  = sgam + 256;
    sbias[tid] = bi[tid] + bo[tid];     // harness inputs: safe before pdl_wait
    sgam[tid] = lg[tid];
    sbet[tid] = lb[tid];

    if (wid == 0) {
        asm volatile("tcgen05.alloc.cta_group::1.sync.aligned.shared::cta.b32 [%0], %1;"
                     :: "r"(sb), "r"(512u) : "memory");
    }
    if (tid == 0) { MBAR_INIT(sb + 8, 1); MBAR_INIT(sb + 16, 1); }
    __syncthreads();
    uint32_t tmem;
    asm volatile("ld.shared.b32 %0, [%1];" : "=r"(tmem) : "r"(sb));

    int arowi[4], acol[4], adst[4], browi[8], bcol[8], bdst[8];
#pragma unroll
    for (int u = 0; u < 4; u++) {
        int idx = u * 256 + tid;
        arowi[u] = idx >> 3;
        int q = idx & 7;
        acol[u] = q * 8;
        adst[u] = SWZ128(arowi[u] * 128 + q * 16);
    }
#pragma unroll
    for (int u = 0; u < 8; u++) {
        int idx = u * 256 + tid;
        browi[u] = idx >> 3;
        int q = idx & 7;
        bcol[u] = q * 8;
        bdst[u] = SWZ128(browi[u] * 128 + q * 16);
    }

    auto issue_A = [&](int ck) {
        const __nv_bfloat16* Ag;
        int koff;
        if (L0MODE) { Ag = g_A0 + (size_t)m0 * ASTR; koff = ck * 64; }
        else {
            int sg = ck >> 2;
            Ag = g_Abf[segA[sg]] + (size_t)m0 * ASTR;
            koff = (ck & 3) * 64;
        }
        int buf = ck & 1;
#pragma unroll
        for (int u = 0; u < 4; u++)
            CP_ASYNC16(sb + aoff[buf] + adst[u], Ag + (size_t)arowi[u] * ASTR + acol[u] + koff);
    };
    auto issue_B = [&](int ck) {
        const __nv_bfloat16* Bg;
        int koff;
        if (L0MODE) { Bg = Wp; koff = ck * 64; }
        else {
            int sg = ck >> 2;
            Bg = Wp + (size_t)sg * DD * DD;
            koff = (ck & 3) * 64;
        }
        int buf = ck & 1;
#pragma unroll
        for (int u = 0; u < 8; u++)
            CP_ASYNC16(sb + boff[buf] + bdst[u], Bg + (size_t)browi[u] * BSTR + bcol[u] + koff);
    };

    // B of chunk 0 overlaps the producer's tail (Wp finalized kernels ago)
    issue_B(0);
    CP_COMMIT;
    pdl_wait();                        // A operand from producer (spmm / ag0)
    issue_A(0);
    CP_COMMIT;

    int ph[2] = {0, 0};
    for (int chunk = 0; chunk < NCH; chunk++) {
        int buf = chunk & 1;
        if (chunk + 1 < NCH) {
            int nbuf = (chunk + 1) & 1;
            if (chunk >= 1) {
                if (nbuf == 0) { MBAR_WAIT(sb + 8, ph[0]); ph[0] ^= 1; }
                else           { MBAR_WAIT(sb + 16, ph[1]); ph[1] ^= 1; }
            }
            issue_B(chunk + 1);
            issue_A(chunk + 1);
            CP_COMMIT;
            CP_WAIT1;                  // drains all of chunk's groups
        } else {
            CP_WAIT0;
        }
        __syncthreads();
        if (wid == 0) {
            asm volatile("fence.proxy.async.shared::cta;" ::: "memory");
            if (elect_one()) {
                uint64_t ad = MK_DESC(sb + aoff[buf]);
                uint64_t bd = MK_DESC(sb + boff[buf]);
#pragma unroll
                for (int st = 0; st < 4; st++)
                    mma_f16_ss(tmem, ad + st * 2, bd + st * 2, IDESC, !(chunk == 0 && st == 0));
                asm volatile(
                    "tcgen05.commit.cta_group::1.mbarrier::arrive::one.shared::cluster.b64 [%0];"
                    :: "r"(sb + 8 + buf * 8) : "memory");
            }
        }
        __syncthreads();
    }
    MBAR_WAIT(sb + 8, ph[0]);
    MBAR_WAIT(sb + 16, ph[1]);
    asm volatile("tcgen05.fence::after_thread_sync;" ::: "memory");
    __syncthreads();

    if (wid < 4) {
        int row = m0 + wid * 32 + lid;
        float sum = 0.f, sq = 0.f;
        uint32_t r[32];
        for (int cb = 0; cb < 8; cb++) {
            asm volatile(
                "tcgen05.ld.sync.aligned.32x32b.x32.b32 "
                "{%0,%1,%2,%3,%4,%5,%6,%7,%8,%9,%10,%11,%12,%13,%14,%15,"
                "%16,%17,%18,%19,%20,%21,%22,%23,%24,%25,%26,%27,%28,%29,%30,%31}, [%32];"
                : "=r"(r[0]), "=r"(r[1]), "=r"(r[2]), "=r"(r[3]), "=r"(r[4]), "=r"(r[5]), "=r"(r[6]), "=r"(r[7]),
                  "=r"(r[8]), "=r"(r[9]), "=r"(r[10]), "=r"(r[11]), "=r"(r[12]), "=r"(r[13]), "=r"(r[14]), "=r"(r[15]),
                  "=r"(r[16]), "=r"(r[17]), "=r"(r[18]), "=r"(r[19]), "=r"(r[20]), "=r"(r[21]), "=r"(r[22]), "=r"(r[23]),
                  "=r"(r[24]), "=r"(r[25]), "=r"(r[26]), "=r"(r[27]), "=r"(r[28]), "=r"(r[29]), "=r"(r[30]), "=r"(r[31])
                : "r"(tmem + cb * 32));
            asm volatile("tcgen05.wait::ld.sync.aligned;" ::: "memory");
#pragma unroll
            for (int j = 0; j < 32; j++) {
                int nn = cb * 32 + j;
                float v = __uint_as_float(r[j]) + sbias[nn];
                sum += v; sq += v * v;
            }
        }
        float mean = sum * (1.f / DD);
        float var = sq * (1.f / DD) - mean * mean;
        float rstd = rsqrtf(var + 1e-5f);
        float* __restrict__ Hout = g_H[outbuf];
        for (int cb = 0; cb < 8; cb++) {
            asm volatile(
                "tcgen05.ld.sync.aligned.32x32b.x32.b32 "
                "{%0,%1,%2,%3,%4,%5,%6,%7,%8,%9,%10,%11,%12,%13,%14,%15,"
                "%16,%17,%18,%19,%20,%21,%22,%23,%24,%25,%26,%27,%28,%29,%30,%31}, [%32];"
                : "=r"(r[0]), "=r"(r[1]), "=r"(r[2]), "=r"(r[3]), "=r"(r[4]), "=r"(r[5]), "=r"(r[6]), "=r"(r[7]),
                  "=r"(r[8]), "=r"(r[9]), "=r"(r[10]), "=r"(r[11]), "=r"(r[12]), "=r"(r[13]), "=r"(r[14]), "=r"(r[15]),
                  "=r"(r[16]), "=r"(r[17]), "=r"(r[18]), "=r"(r[19]), "=r"(r[20]), "=r"(r[21]), "=r"(r[22]), "=r"(r[23]),
                  "=r"(r[24]), "=r"(r[25]), "=r"(r[26]), "=r"(r[27]), "=r"(r[28]), "=r"(r[29]), "=r"(r[30]), "=r"(r[31])
                : "r"(tmem + cb * 32));
            asm volatile("tcgen05.wait::ld.sync.aligned;" ::: "memory");
#pragma unroll
            for (int j = 0; j < 32; j++) {
                int nn = cb * 32 + j;
                float v = __uint_as_float(r[j]) + sbias[nn];
                float y = (v - mean) * rstd * sgam[nn] + sbet[nn];
                Hout[(size_t)row * DD + nn] = y > 0.f ? y : 0.f;
            }
        }
    }
    __syncthreads();
    if (wid == 0) {
        asm volatile("tcgen05.relinquish_alloc_permit.cta_group::1.sync.aligned;");
        asm volatile("tcgen05.dealloc.cta_group::1.sync.aligned.b32 %0, %1;" :: "r"(tmem), "r"(512u));
    }
#else
    // ---------------- mma.sync bf16 fallback path (plain sm_103) ----------------
    char* smp = smem + (sb - raw);
    __shared__ float sdsum[128];
    __shared__ float sdsq[128];
    const uint32_t faoff[2] = {1024u, 1024u + FA_BYTES};
    const uint32_t fboff[2] = {1024u + 2 * FA_BYTES, 1024u + 2 * FA_BYTES + FB_BYTES};
    int gid = lid >> 2, t4 = lid & 3;
    int wm = wid >> 1, wn = wid & 1;
    int mrow = wm * 32, ncol = wn * 128;
    float acc[2][16][4];
#pragma unroll
    for (int i = 0; i < 2; i++)
#pragma unroll
        for (int j = 0; j < 16; j++)
#pragma unroll
            for (int q = 0; q < 4; q++) acc[i][j][q] = 0.f;

    pdl_wait();
    for (int chunk = 0; chunk < NCH; chunk++) {
        const __nv_bfloat16* Ag;
        const __nv_bfloat16* Bg;
        int koff;
        if (L0MODE) {
            Ag = g_A0;
            Bg = Wp;
            koff = chunk * 64;
        } else {
            int sg = chunk >> 2, c = chunk & 3;
            Ag = g_Abf[segA[sg]];
            Bg = Wp + (size_t)sg * DD * DD;
            koff = c * 64;
        }
        int buf = chunk & 1;
        __syncthreads();
#pragma unroll
        for (int u = 0; u < 4; u++) {
            int idx = u * 256 + tid;
            int row = idx >> 3, q = idx & 7;
            uint4 v = *(const uint4*)(Ag + (size_t)(m0 + row) * ASTR + koff + q * 8);
            *(uint4*)(smp + faoff[buf] + row * PAD_STRIDE + q * 16) = v;
        }
#pragma unroll
        for (int u = 0; u < 8; u++) {
            int idx = u * 256 + tid;
            int row = idx >> 3, q = idx & 7;
            uint4 v = *(const uint4*)(Bg + (size_t)row * BSTR + koff + q * 8);
            *(uint4*)(smp + fboff[buf] + row * PAD_STRIDE + q * 16) = v;
        }
        __syncthreads();
        const char* ab = smp + faoff[buf];
        const char* bb = smp + fboff[buf];
#pragma unroll
        for (int ks = 0; ks < 4; ks++) {
            int kb = ks * 32;
            uint32_t a[2][4];
#pragma unroll
            for (int ma = 0; ma < 2; ma++) {
                int r0 = mrow + ma * 16 + gid;
                a[ma][0] = *(const uint32_t*)(ab + r0 * PAD_STRIDE + kb + t4 * 4);
                a[ma][1] = *(const uint32_t*)(ab + (r0 + 8) * PAD_STRIDE + kb + t4 * 4);
                a[ma][2] = *(const uint32_t*)(ab + r0 * PAD_STRIDE + kb + 16 + t4 * 4);
                a[ma][3] = *(const uint32_t*)(ab + (r0 + 8) * PAD_STRIDE + kb + 16 + t4 * 4);
            }
#pragma unroll
            for (int nb = 0; nb < 16; nb++) {
                int cc = ncol + nb * 8 + gid;
                uint32_t b0 = *(const uint32_t*)(bb + cc * PAD_STRIDE + kb + t4 * 4);
                uint32_t b1 = *(const uint32_t*)(bb + cc * PAD_STRIDE + kb + 16 + t4 * 4);
#pragma unroll
                for (int ma = 0; ma < 2; ma++) {
                    asm volatile(
                        "mma.sync.aligned.m16n8k16.row.col.f32.bf16.bf16.f32 "
                        "{%0,%1,%2,%3}, {%4,%5,%6,%7}, {%8,%9}, {%0,%1,%2,%3};"
                        : "+f"(acc[ma][nb][0]), "+f"(acc[ma][nb][1]),
                          "+f"(acc[ma][nb][2]), "+f"(acc[ma][nb][3])
                        : "r"(a[ma][0]), "r"(a[ma][1]), "r"(a[ma][2]), "r"(a[ma][3]),
                          "r"(b0), "r"(b1));
                }
            }
        }
    }
    __syncthreads();
    if (tid < 128) { sdsum[tid] = 0.f; sdsq[tid] = 0.f; }
    __syncthreads();
    float* __restrict__ Hout = g_H[outbuf];
#pragma unroll
    for (int ma = 0; ma < 2; ma++) {
#pragma unroll
        for (int nb = 0; nb < 16; nb++) {
#pragma unroll
            for (int q = 0; q < 4; q++) {
                int row = mrow + ma * 16 + gid + ((q >= 2) ? 8 : 0);
                int col = ncol + nb * 8 + t4 * 2 + (q & 1);
                float v = acc[ma][nb][q] + __ldg(&bi[col]) + __ldg(&bo[col]);
                Hout[(size_t)(m0 + row) * DD + col] = v;
                atomicAdd(&sdsum[row], v);
                atomicAdd(&sdsq[row], v * v);
            }
        }
    }
    __syncthreads();
    for (int r = wid; r < 128; r += 8) {
        float mean = sdsum[r] * (1.f / DD);
        float var = sdsq[r] * (1.f / DD) - mean * mean;
        float rstd = rsqrtf(var + 1e-5f);
#pragma unroll
        for (int u = 0; u < 8; u++) {
            int col = u * 32 + lid;
            float v = Hout[(size_t)(m0 + r) * DD + col];
            float y = (v - mean) * rstd * __ldg(&lg[col]) + __ldg(&lb[col]);
            Hout[(size_t)(m0 + r) * DD + col] = y > 0.f ? y : 0.f;
        }
    }
#endif
}

// ---------------- per-layer SpMM: 4 nodes/block, 64 thr/node, float4 gathers --
__global__ void k_spmm(int buf) {
    const float4* __restrict__ H4 = (const float4*)g_H[buf];
    int t = threadIdx.x;
    int grp = t >> 6;            // node within block (0..3)
    int c4 = t & 63;             // float4 column (64 x 4 = 256 floats)
    int n = blockIdx.x * 4 + grp;
    pdl_wait();                  // g_H[buf] from previous GEMM
    int beg = g_off[n], end = g_off[n + 1];
    float4 ai = make_float4(0.f, 0.f, 0.f, 0.f);
    float4 ao = make_float4(0.f, 0.f, 0.f, 0.f);
    int j = beg;
    if (j < end && (j & 1)) {
        int2 e = g_csrw[j];
        float4 v = __ldg(&H4[(size_t)(e.x >> 1) * 64 + c4]);
        float w = __int_as_float(e.y);
        float wi = (e.x & 1) ? w : 0.f, wo = (e.x & 1) ? 0.f : w;
        ai.x = fmaf(wi, v.x, ai.x); ai.y = fmaf(wi, v.y, ai.y);
        ai.z = fmaf(wi, v.z, ai.z); ai.w = fmaf(wi, v.w, ai.w);
        ao.x = fmaf(wo, v.x, ao.x); ao.y = fmaf(wo, v.y, ao.y);
        ao.z = fmaf(wo, v.z, ao.z); ao.w = fmaf(wo, v.w, ao.w);
        j++;
    }
    for (; j + 4 <= end; j += 4) {
        int4 p0 = *(const int4*)&g_csrw[j];
        int4 p1 = *(const int4*)&g_csrw[j + 2];
        float4 v0 = __ldg(&H4[(size_t)(p0.x >> 1) * 64 + c4]);
        float4 v1 = __ldg(&H4[(size_t)(p0.z >> 1) * 64 + c4]);
        float4 v2 = __ldg(&H4[(size_t)(p1.x >> 1) * 64 + c4]);
        float4 v3 = __ldg(&H4[(size_t)(p1.z >> 1) * 64 + c4]);
        float w0 = __int_as_float(p0.y), w1 = __int_as_float(p0.w);
        float w2 = __int_as_float(p1.y), w3 = __int_as_float(p1.w);
        float wi0 = (p0.x & 1) ? w0 : 0.f, wo0 = (p0.x & 1) ? 0.f : w0;
        float wi1 = (p0.z & 1) ? w1 : 0.f, wo1 = (p0.z & 1) ? 0.f : w1;
        float wi2 = (p1.x & 1) ? w2 : 0.f, wo2 = (p1.x & 1) ? 0.f : w2;
        float wi3 = (p1.z & 1) ? w3 : 0.f, wo3 = (p1.z & 1) ? 0.f : w3;
        ai.x = fmaf(wi0, v0.x, ai.x); ai.y = fmaf(wi0, v0.y, ai.y);
        ai.z = fmaf(wi0, v0.z, ai.z); ai.w = fmaf(wi0, v0.w, ai.w);
        ao.x = fmaf(wo0, v0.x, ao.x); ao.y = fmaf(wo0, v0.y, ao.y);
        ao.z = fmaf(wo0, v0.z, ao.z); ao.w = fmaf(wo0, v0.w, ao.w);
        ai.x = fmaf(wi1, v1.x, ai.x); ai.y = fmaf(wi1, v1.y, ai.y);
        ai.z = fmaf(wi1, v1.z, ai.z); ai.w = fmaf(wi1, v1.w, ai.w);
        ao.x = fmaf(wo1, v1.x, ao.x); ao.y = fmaf(wo1, v1.y, ao.y);
        ao.z = fmaf(wo1, v1.z, ao.z); ao.w = fmaf(wo1, v1.w, ao.w);
        ai.x = fmaf(wi2, v2.x, ai.x); ai.y = fmaf(wi2, v2.y, ai.y);
        ai.z = fmaf(wi2, v2.z, ai.z); ai.w = fmaf(wi2, v2.w, ai.w);
        ao.x = fmaf(wo2, v2.x, ao.x); ao.y = fmaf(wo2, v2.y, ao.y);
        ao.z = fmaf(wo2, v2.z, ao.z); ao.w = fmaf(wo2, v2.w, ao.w);
        ai.x = fmaf(wi3, v3.x, ai.x); ai.y = fmaf(wi3, v3.y, ai.y);
        ai.z = fmaf(wi3, v3.z, ai.z); ai.w = fmaf(wi3, v3.w, ai.w);
        ao.x = fmaf(wo3, v3.x, ao.x); ao.y = fmaf(wo3, v3.y, ao.y);
        ao.z = fmaf(wo3, v3.z, ao.z); ao.w = fmaf(wo3, v3.w, ao.w);
    }
    for (; j < end; j++) {
        int2 e = g_csrw[j];
        float4 v = __ldg(&H4[(size_t)(e.x >> 1) * 64 + c4]);
        float w = __int_as_float(e.y);
        float wi = (e.x & 1) ? w : 0.f, wo = (e.x & 1) ? 0.f : w;
        ai.x = fmaf(wi, v.x, ai.x); ai.y = fmaf(wi, v.y, ai.y);
        ai.z = fmaf(wi, v.z, ai.z); ai.w = fmaf(wi, v.w, ai.w);
        ao.x = fmaf(wo, v.x, ao.x); ao.y = fmaf(wo, v.y, ao.y);
        ao.z = fmaf(wo, v.z, ao.z); ao.w = fmaf(wo, v.w, ao.w);
    }
    // hi/lo split, packed 8B stores (4 bf16 per array per thread)
    int ou = n * 64 + c4;
    union { __nv_bfloat162 h2[2]; uint2 u; } pk;
    __nv_bfloat16 h0, h1, h2b, h3;
    h0 = __float2bfloat16(ai.x); h1 = __float2bfloat16(ai.y);
    h2b = __float2bfloat16(ai.z); h3 = __float2bfloat16(ai.w);
    pk.h2[0] = __nv_bfloat162(h0, h1); pk.h2[1] = __nv_bfloat162(h2b, h3);
    ((uint2*)g_Abf[0])[ou] = pk.u;
    pk.h2[0] = __nv_bfloat162(__float2bfloat16(ai.x - __bfloat162float(h0)),
                              __float2bfloat16(ai.y - __bfloat162float(h1)));
    pk.h2[1] = __nv_bfloat162(__float2bfloat16(ai.z - __bfloat162float(h2b)),
                              __float2bfloat16(ai.w - __bfloat162float(h3)));
    ((uint2*)g_Abf[1])[ou] = pk.u;
    h0 = __float2bfloat16(ao.x); h1 = __float2bfloat16(ao.y);
    h2b = __float2bfloat16(ao.z); h3 = __float2bfloat16(ao.w);
    pk.h2[0] = __nv_bfloat162(h0, h1); pk.h2[1] = __nv_bfloat162(h2b, h3);
    ((uint2*)g_Abf[2])[ou] = pk.u;
    pk.h2[0] = __nv_bfloat162(__float2bfloat16(ao.x - __bfloat162float(h0)),
                              __float2bfloat16(ao.y - __bfloat162float(h1)));
    pk.h2[1] = __nv_bfloat162(__float2bfloat16(ao.z - __bfloat162float(h2b)),
                              __float2bfloat16(ao.w - __bfloat162float(h3)));
    ((uint2*)g_Abf[3])[ou] = pk.u;
}

// ---------------- fragment pooling + LN + mask + reg loss (fused) ------------
__global__ void k_frag(int buf, const float* __restrict__ fg, const float* __restrict__ fb,
                       float* __restrict__ emb, float* __restrict__ fmask,
                       const float* __restrict__ w0r, const float* __restrict__ bo0r,
                       const float* __restrict__ Wr, const float* __restrict__ bor,
                       float* __restrict__ regout) {
    int t = threadIdx.x;
    if (blockIdx.x == BBG) {
        // reg-loss: reads only harness inputs — no pdl_wait needed
        __shared__ float r[256];
        float a = 0.f;
        for (int i = t; i < DIN * DD; i += 256) a += fabsf(w0r[i]);
        a += fabsf(bo0r[t]);
        for (int i = t; i < 3 * DD * DD; i += 256) a += fabsf(Wr[i]);
        for (int i = t; i < 3 * DD; i += 256) a += fabsf(bor[i]);
        r[t] = a;
        __syncthreads();
        for (int o = 128; o > 0; o >>= 1) {
            if (t < o) r[t] += r[t + o];
            __syncthreads();
        }
        if (t == 0) regout[0] = r[0];
        return;
    }
    const float* __restrict__ H = g_H[buf];
    int b = blockIdx.x;
    int lane = t & 31, wd = t >> 5;
    __shared__ float sacc[KF][DD];
    __shared__ int   sfrag[NPGX];
    __shared__ int   scnt[KF];
    __shared__ float w1[8], w2[8];
#pragma unroll
    for (int kf = 0; kf < KF; kf++) sacc[kf][t] = 0.f;
    if (t < NPGX) sfrag[t] = g_frag[b * NPGX + t];   // k_setup output: complete
    pdl_wait();                        // H from final GEMM
    __syncthreads();
    int base = b * NPGX;
    int cnt_local = 0;
    for (int p = 0; p < NPGX; p++) {
        int f = sfrag[p];
        float v = H[(size_t)(base + p) * DD + t];
        sacc[f][t] += v;
        if (t == f) cnt_local++;
    }
    if (t < KF) scnt[t] = cnt_local;
    __syncthreads();
    for (int kf = 0; kf < KF; kf++) {
        float acc = sacc[kf][t];
        float s1 = acc, s2 = acc * acc;
#pragma unroll
        for (int o = 16; o > 0; o >>= 1) {
            s1 += __shfl_xor_sync(0xFFFFFFFFu, s1, o);
            s2 += __shfl_xor_sync(0xFFFFFFFFu, s2, o);
        }
        if (lane == 0) { w1[wd] = s1; w2[wd] = s2; }
        __syncthreads();
        float t1 = 0.f, t2 = 0.f;
#pragma unroll
        for (int i = 0; i < 8; i++) { t1 += w1[i]; t2 += w2[i]; }
        float m = t1 * (1.f / DD);
        float var = t2 * (1.f / DD) - m * m;
        float y = (acc - m) * rsqrtf(var + 1e-5f) * fg[t] + fb[t];
        emb[(size_t)(b * KF + kf) * DD + t] = y;
        if (t == 0) fmask[b * KF + kf] = (scnt[kf] > 0) ? 1.f : 0.f;
        __syncthreads();
    }
}

// ---------------- PDL launch helper ----------------
template <typename Kern, typename... Args>
static inline void launch_pdl(Kern k, dim3 grid, dim3 block, size_t shmem, Args... args) {
    cudaLaunchConfig_t cfg = {};
    cfg.gridDim = grid;
    cfg.blockDim = block;
    cfg.dynamicSmemBytes = shmem;
    cfg.stream = 0;
    cudaLaunchAttribute attr[1];
    attr[0].id = cudaLaunchAttributeProgrammaticStreamSerialization;
    attr[0].val.programmaticStreamSerializationAllowed = 1;
    cfg.attrs = attr;
    cfg.numAttrs = 1;
    cudaLaunchKernelEx(&cfg, k, args...);
}

// ---------------- launch ----------------
extern "C" void kernel_launch(void* const* d_in, const int* in_sizes, int n_in,
                              void* d_out, int out_size) {
    const float* x   = (const float*)d_in[0];
    const int*   ei  = (const int*)d_in[1];
    const void*  msk = d_in[2];
    const float* s   = (const float*)d_in[3];
    const float* Wi0 = (const float*)d_in[5];
    const float* Wo0 = (const float*)d_in[6];
    const float* bi0 = (const float*)d_in[7];
    const float* bo0 = (const float*)d_in[8];
    const float* Wi  = (const float*)d_in[9];
    const float* Wo  = (const float*)d_in[10];
    const float* bi  = (const float*)d_in[11];
    const float* bo  = (const float*)d_in[12];
    const float* lg  = (const float*)d_in[13];
    const float* lb  = (const float*)d_in[14];
    const float* fg  = (const float*)d_in[15];
    const float* fb  = (const float*)d_in[16];
    float* out = (float*)d_out;

    const int* src = ei;
    const int* dst = ei + NE;

    cudaFuncSetAttribute(k_gemm_tc<24, false>, cudaFuncAttributeMaxDynamicSharedMemorySize, SMEM_NEED);
    cudaFuncSetAttribute(k_gemm_tc<3, true>, cudaFuncAttributeMaxDynamicSharedMemorySize, SMEM_NEED);

    k_setup<<<(NN * 32 + 255) / 256, 256>>>(s, dst, Wi, Wo, Wi0, Wo0, x);
    k_scan<<<1, 1024>>>((const unsigned char*)msk);
    launch_pdl(k_csr, dim3((NE + 255) / 256), dim3(256), 0, src, dst, msk);
    launch_pdl(k_ag0, dim3(NN / 8), dim3(256), (size_t)0);

    __nv_bfloat16* wp_dev = nullptr;
    cudaGetSymbolAddress((void**)&wp_dev, g_Wp);
    __nv_bfloat16* w0p_dev = nullptr;
    cudaGetSymbolAddress((void**)&w0p_dev, g_W0p);

    launch_pdl(k_gemm_tc<3, true>, dim3(NN / 128), dim3(256), (size_t)SMEM_NEED,
               (const __nv_bfloat16*)w0p_dev, bi0, bo0, lg, lb, 0);

    int cur = 0;
    for (int l = 0; l < 3; l++) {
        launch_pdl(k_spmm, dim3(NN / 4), dim3(256), (size_t)0, cur);
        launch_pdl(k_gemm_tc<24, false>, dim3(NN / 128), dim3(256), (size_t)SMEM_NEED,
                   (const __nv_bfloat16*)(wp_dev + (size_t)l * 6 * DD * DD),
                   bi + l * DD, bo + l * DD,
                   lg + (l + 1) * DD, lb + (l + 1) * DD, 1 - cur);
        cur = 1 - cur;
    }

    launch_pdl(k_frag, dim3(BBG + 1), dim3(256), (size_t)0,
               cur, fg, fb, out, out + BBG * KF * DD,
               Wo0, bo0, Wo, bo, out + BBG * KF * DD + BBG * KF);
}